// round 13
// baseline (speedup 1.0000x reference)
#include <cuda_runtime.h>
#include <cstdint>
#include <math.h>

// ---------------- problem dims ----------------
#define B_ROWS 16384
#define D_VIS  1024
#define D_H    256
#define E_NUM  4
#define G_NUM  5000
#define MAP_   128
#define SCVI_  30
#define N_GD2  (G_NUM*2)

// ---------------- tf32 mma.sync GEMM tile config ----------------
#define BM 128
#define BN 128
#define BK 32
#define STAGES 3
#define NTHREADS 256
#define AS_STRIDE 40
#define BS_STRIDE 132
#define AS_SIZE (BM*AS_STRIDE)
#define BS_SIZE (BK*BS_STRIDE)
#define STAGE_FLOATS (AS_SIZE + BS_SIZE)
#define SMEM_BYTES (STAGES*STAGE_FLOATS*4)
#define MAX_TILES 132
#define ES_STRIDE 132

// ---------------- scratch ----------------
__device__ float g_four[(size_t)B_ROWS*2*MAP_];
__device__ float g_z   [(size_t)B_ROWS*D_H];
__device__ float g_zf  [(size_t)B_ROWS*D_H];
__device__ float g_tpre[(size_t)B_ROWS*D_H];
__device__ float g_t   [(size_t)B_ROWS*D_H];
__device__ float g_a1  [(size_t)B_ROWS*128];
__device__ float g_f1  [(size_t)B_ROWS*64];
__device__ float g_h   [(size_t)MAX_TILES*BM*1024];
__device__ int   g_eid [B_ROWS];
__device__ float g_gate[B_ROWS];
__device__ int   g_perm[MAX_TILES*BM];
__device__ int   g_counts[E_NUM];
__device__ int   g_cursor[E_NUM];
__device__ int   g_padoff[E_NUM+1];
__device__ float g_w_apfh[256*192];   // packed+rounded [ap1 | fh1] N=192

// ---------------- helpers ----------------
__device__ __forceinline__ float gelu_exact(float x) {
    return 0.5f * x * (1.0f + erff(x * 0.70710678118654752440f));
}
__device__ __forceinline__ uint32_t f2tf(float f) {
    uint32_t o; asm("cvt.rna.tf32.f32 %0, %1;" : "=r"(o) : "f"(f)); return o;
}
__device__ __forceinline__ float rnd_tf(float f) { return __uint_as_float(f2tf(f)); }

__device__ __forceinline__ void mma8(float* c, const uint32_t* a, const uint32_t* b) {
    asm volatile("mma.sync.aligned.m16n8k8.row.col.f32.tf32.tf32.f32 "
        "{%0,%1,%2,%3}, {%4,%5,%6,%7}, {%8,%9}, {%0,%1,%2,%3};"
        : "+f"(c[0]), "+f"(c[1]), "+f"(c[2]), "+f"(c[3])
        : "r"(a[0]), "r"(a[1]), "r"(a[2]), "r"(a[3]), "r"(b[0]), "r"(b[1]));
}
__device__ __forceinline__ void cp_async16(float* dst_smem, const float* src, int src_bytes) {
    uint32_t d = (uint32_t)__cvta_generic_to_shared(dst_smem);
    asm volatile("cp.async.cg.shared.global [%0], [%1], 16, %2;\n"
                 :: "r"(d), "l"(src), "r"(src_bytes));
}
__device__ __forceinline__ void cp16f(float* dst_smem, const float* src) {
    uint32_t d = (uint32_t)__cvta_generic_to_shared(dst_smem);
    asm volatile("cp.async.cg.shared.global [%0], [%1], 16;\n" :: "r"(d), "l"(src));
}
__device__ __forceinline__ void cp_commit() { asm volatile("cp.async.commit_group;\n"); }
template<int N> __device__ __forceinline__ void cp_wait() {
    asm volatile("cp.async.wait_group %0;\n" :: "n"(N));
}

// pack + round apfh weights only (ap1 [256,128] | fh1 [256,64] -> [256,192])
__global__ void k_round_apfh(const float* __restrict__ apW1, const float* __restrict__ fhW1) {
    int i = blockIdx.x * blockDim.x + threadIdx.x;   // float4 index
    if (i >= 8192 + 4096) return;
    const float* src; int off, dsti;
    if (i < 8192) { src = apW1; off = i; int row = off >> 5, c4 = off & 31; dsti = row*48 + c4; }
    else          { src = fhW1; off = i - 8192; int row = off >> 4, c4 = off & 15; dsti = row*48 + 32 + c4; }
    float4 v = ((const float4*)src)[off];
    v.x = rnd_tf(v.x); v.y = rnd_tf(v.y); v.z = rnd_tf(v.z); v.w = rnd_tf(v.w);
    ((float4*)g_w_apfh)[dsti] = v;
}

// Load one 128x32 A tile (optional perm-gather; row<0 -> zero) and one
// 32x128 B tile (column-guarded vs N only when needed) via cp.async.
__device__ __forceinline__ void issue_tile(
    float* stage,
    const float* __restrict__ A, int lda,
    const float* __restrict__ W, int N,
    int m0, int n0, int k0, const int* __restrict__ perm)
{
    float* As = stage;
    float* Bs = stage + AS_SIZE;
    const int tid = threadIdx.x;
    int ar = tid >> 1;
    int ac = (tid & 1) * 16;
    if (perm) {
        int rowg = perm[m0 + ar];
        const float* srcA = A + (size_t)(rowg < 0 ? 0 : rowg) * lda + k0 + ac;
        int szA = (rowg >= 0) ? 16 : 0;
        #pragma unroll
        for (int i = 0; i < 4; i++)
            cp_async16(As + ar*AS_STRIDE + ac + i*4, srcA + i*4, szA);
    } else {
        const float* srcA = A + (size_t)(m0 + ar) * lda + k0 + ac;
        #pragma unroll
        for (int i = 0; i < 4; i++)
            cp16f(As + ar*AS_STRIDE + ac + i*4, srcA + i*4);
    }
    int br = tid >> 3;
    int bc = (tid & 7) * 16;
    const float* srcB = W + (size_t)(k0 + br) * N + n0 + bc;
    if (n0 + BN <= N) {
        #pragma unroll
        for (int i = 0; i < 4; i++)
            cp16f(Bs + br*BS_STRIDE + bc + i*4, srcB + i*4);
    } else {
        #pragma unroll
        for (int i = 0; i < 4; i++) {
            int col = n0 + bc + i*4;
            int bytes = (N - col) * 4;
            bytes = bytes < 0 ? 0 : (bytes > 16 ? 16 : bytes);
            cp_async16(Bs + br*BS_STRIDE + bc + i*4, bytes > 0 ? (srcB + i*4) : W, bytes);
        }
    }
}

// load raw fragment bits for one k-slice (no conversion -> no dependency
// beyond the LDS itself; conversion happens at use time)
__device__ __forceinline__ void load_frag_slice(
    const uint32_t* __restrict__ As, const uint32_t* __restrict__ Bs,
    int mw, int nw, int g, int t4, int ks,
    uint32_t af[4][4], uint32_t bf[4][2])
{
    const int k0s = ks * 8;
    #pragma unroll
    for (int mi = 0; mi < 4; mi++) {
        int r = mw + mi*16 + g;
        uint2 pa = *(const uint2*)(As + (r  )*AS_STRIDE + k0s + 2*t4);
        uint2 pb = *(const uint2*)(As + (r+8)*AS_STRIDE + k0s + 2*t4);
        af[mi][0] = pa.x; af[mi][2] = pa.y;
        af[mi][1] = pb.x; af[mi][3] = pb.y;
    }
    #pragma unroll
    for (int ni = 0; ni < 4; ni++) {
        int c = nw + ni*8 + g;
        bf[ni][0] = Bs[(k0s + 2*t4    )*BS_STRIDE + c];
        bf[ni][1] = Bs[(k0s + 2*t4 + 1)*BS_STRIDE + c];
    }
}

// Pipelined tf32 GEMM: 3-stage gmem->smem cp.async pipeline (one sync per
// k-tile) + 2-deep register fragment pipeline (loads of slice ks+1 overlap
// the 16 MMAs of slice ks). CVTA/CVTB apply cvt.rna.tf32 at use time
// (bit-identical to pre-rounded operands).
template<bool CVTA, bool CVTB>
__device__ __forceinline__ void gemm_tf32(
    float acc[4][4][4],
    const float* __restrict__ A, int lda, int K,
    const float* __restrict__ W, int N,
    int m0, int n0, const int* __restrict__ perm, float* sm)
{
    const int KT = K >> 5;
    #pragma unroll
    for (int s = 0; s < STAGES-1; s++) {
        if (s < KT) issue_tile(sm + s*STAGE_FLOATS, A, lda, W, N, m0, n0, s*BK, perm);
        cp_commit();
    }
    cp_wait<STAGES-2>();
    __syncthreads();

    const int warp = threadIdx.x >> 5, lane = threadIdx.x & 31;
    const int mw = (warp >> 2) * 64, nw = (warp & 3) * 32;
    const int g = lane >> 2, t4 = lane & 3;

    for (int kt = 0; kt < KT; kt++) {
        const float* Asf = sm + (kt%STAGES)*STAGE_FLOATS;
        const uint32_t* As = (const uint32_t*)Asf;
        const uint32_t* Bs = (const uint32_t*)(Asf + AS_SIZE);

        uint32_t af[2][4][4], bf[2][4][2];
        load_frag_slice(As, Bs, mw, nw, g, t4, 0, af[0], bf[0]);
        #pragma unroll
        for (int ks = 0; ks < BK/8; ks++) {
            const int cur = ks & 1, nxt = cur ^ 1;
            if (ks + 1 < BK/8)
                load_frag_slice(As, Bs, mw, nw, g, t4, ks+1, af[nxt], bf[nxt]);
            if (CVTA) {
                #pragma unroll
                for (int mi = 0; mi < 4; mi++)
                    #pragma unroll
                    for (int j = 0; j < 4; j++)
                        af[cur][mi][j] = f2tf(__uint_as_float(af[cur][mi][j]));
            }
            if (CVTB) {
                #pragma unroll
                for (int ni = 0; ni < 4; ni++) {
                    bf[cur][ni][0] = f2tf(__uint_as_float(bf[cur][ni][0]));
                    bf[cur][ni][1] = f2tf(__uint_as_float(bf[cur][ni][1]));
                }
            }
            #pragma unroll
            for (int mi = 0; mi < 4; mi++)
                #pragma unroll
                for (int ni = 0; ni < 4; ni++)
                    mma8(acc[mi][ni], af[cur][mi], bf[cur][ni]);
        }
        int pre = kt + STAGES - 1;
        if (pre < KT) issue_tile(sm + (pre%STAGES)*STAGE_FLOATS, A, lda, W, N, m0, n0, pre*BK, perm);
        cp_commit();
        cp_wait<STAGES-2>();
        __syncthreads();
    }
}

#define FRAG_IDX \
    const int warp = threadIdx.x >> 5, lane = threadIdx.x & 31; \
    const int mw = (warp >> 2) * 64, nw = (warp & 3) * 32; \
    const int g = lane >> 2, t4 = lane & 3;

// ---------------- stage kernels ----------------
// k_four also performs the perm/counter init
__global__ void k_four(const float* __restrict__ pos, const float* __restrict__ fB) {
    int gtid = blockIdx.x * 256 + threadIdx.x;
    if (gtid < MAX_TILES*BM) g_perm[gtid] = -1;
    if (gtid < E_NUM) { g_counts[gtid] = 0; g_cursor[gtid] = 0; }

    int w = threadIdx.x >> 5, lane = threadIdx.x & 31;
    int row = blockIdx.x * 8 + w;
    float p0 = pos[row*3+0], p1 = pos[row*3+1], p2 = pos[row*3+2];
    #pragma unroll
    for (int i = 0; i < 4; i++) {
        int c = lane + 32*i;
        float xp = 6.283185307179586477f * (p0*fB[c] + p1*fB[MAP_+c] + p2*fB[2*MAP_+c]);
        float s, co;
        sincosf(xp, &s, &co);
        g_four[(size_t)row*256 + c]       = rnd_tf(s);
        g_four[(size_t)row*256 + 128 + c] = rnd_tf(co);
    }
}

__global__ void __launch_bounds__(NTHREADS, 2)
k_gemm_z(const float* __restrict__ vis, const float* __restrict__ pos_W,
         const float* __restrict__ img_W,
         const float* __restrict__ img_b, const float* __restrict__ pos_b) {
    extern __shared__ float sm[];
    float acc[4][4][4] = {};
    int m0 = blockIdx.y * BM, n0 = blockIdx.x * BN;
    FRAG_IDX
    gemm_tf32<false, true>(acc, g_four, 256, 256, pos_W, 256, m0, n0, nullptr, sm);
    #pragma unroll
    for (int mi = 0; mi < 4; mi++)
        #pragma unroll
        for (int ni = 0; ni < 4; ni++) {
            int c0 = n0 + nw + ni*8 + t4*2;
            acc[mi][ni][0] = gelu_exact(acc[mi][ni][0] + pos_b[c0]);
            acc[mi][ni][1] = gelu_exact(acc[mi][ni][1] + pos_b[c0+1]);
            acc[mi][ni][2] = gelu_exact(acc[mi][ni][2] + pos_b[c0]);
            acc[mi][ni][3] = gelu_exact(acc[mi][ni][3] + pos_b[c0+1]);
        }
    gemm_tf32<true, true>(acc, vis, D_VIS, D_VIS, img_W, 256, m0, n0, nullptr, sm);
    #pragma unroll
    for (int mi = 0; mi < 4; mi++)
        #pragma unroll
        for (int ni = 0; ni < 4; ni++) {
            int r0 = m0 + mw + mi*16 + g, r1 = r0 + 8;
            int c0 = n0 + nw + ni*8 + t4*2, c1 = c0 + 1;
            g_z[(size_t)r0*256 + c0] = acc[mi][ni][0] + img_b[c0];
            g_z[(size_t)r0*256 + c1] = acc[mi][ni][1] + img_b[c1];
            g_z[(size_t)r1*256 + c0] = acc[mi][ni][2] + img_b[c0];
            g_z[(size_t)r1*256 + c1] = acc[mi][ni][3] + img_b[c1];
        }
}

__global__ void k_router(const float* __restrict__ grad,
                         const float* __restrict__ rW, const float* __restrict__ rb) {
    int w = threadIdx.x >> 5, lane = threadIdx.x & 31;
    int row = blockIdx.x * 8 + w;
    float4 s = make_float4(0.f,0.f,0.f,0.f);
    #pragma unroll
    for (int i = 0; i < 8; i++) {
        int k = lane + 32*i;
        float zv = g_z[(size_t)row*256 + k];
        float4 wv = *(const float4*)(rW + k*4);
        s.x = fmaf(zv, wv.x, s.x); s.y = fmaf(zv, wv.y, s.y);
        s.z = fmaf(zv, wv.z, s.z); s.w = fmaf(zv, wv.w, s.w);
    }
    #pragma unroll
    for (int off = 16; off; off >>= 1) {
        s.x += __shfl_down_sync(0xffffffffu, s.x, off);
        s.y += __shfl_down_sync(0xffffffffu, s.y, off);
        s.z += __shfl_down_sync(0xffffffffu, s.z, off);
        s.w += __shfl_down_sync(0xffffffffu, s.w, off);
    }
    if (lane == 0) {
        float gv = grad[row];
        float4 wg = *(const float4*)(rW + 256*4);
        float l0 = s.x + gv*wg.x + rb[0];
        float l1 = s.y + gv*wg.y + rb[1];
        float l2 = s.z + gv*wg.z + rb[2];
        float l3 = s.w + gv*wg.w + rb[3];
        float m = l0; int am = 0;
        if (l1 > m) { m = l1; am = 1; }
        if (l2 > m) { m = l2; am = 2; }
        if (l3 > m) { m = l3; am = 3; }
        float sum = expf(l0-m) + expf(l1-m) + expf(l2-m) + expf(l3-m);
        g_eid[row]  = am;
        g_gate[row] = 1.0f / sum;
        atomicAdd(&g_counts[am], 1);
    }
}

__global__ void k_offsets() {
    int off = 0;
    for (int e = 0; e < E_NUM; e++) {
        g_padoff[e] = off;
        off += ((g_counts[e] + BM - 1) / BM) * BM;
    }
    g_padoff[E_NUM] = off;
}

__global__ void k_scatter() {
    int row = blockIdx.x * 256 + threadIdx.x;
    int e = g_eid[row];
    int slot = g_padoff[e] + atomicAdd(&g_cursor[e], 1);
    g_perm[slot] = row;
}

__device__ __forceinline__ int tile_expert(int m0) {
    int e = 0;
    while (e < E_NUM-1 && m0 >= g_padoff[e+1]) e++;
    return e;
}

__global__ void __launch_bounds__(NTHREADS, 2)
k_moe1(const float* __restrict__ eW1, const float* __restrict__ eb1) {
    int m0 = blockIdx.y * BM;
    if (m0 >= g_padoff[E_NUM]) return;
    extern __shared__ float sm[];
    int e = tile_expert(m0);
    const float* W1 = eW1 + (size_t)e * 256 * 1024;
    float acc[4][4][4] = {};
    int n0 = blockIdx.x * BN;
    gemm_tf32<true, true>(acc, g_z, 256, 256, W1, 1024, m0, n0, g_perm, sm);
    FRAG_IDX
    #pragma unroll
    for (int mi = 0; mi < 4; mi++)
        #pragma unroll
        for (int ni = 0; ni < 4; ni++) {
            int r0 = m0 + mw + mi*16 + g, r1 = r0 + 8;
            int c0 = n0 + nw + ni*8 + t4*2, c1 = c0 + 1;
            g_h[(size_t)r0*1024 + c0] = rnd_tf(gelu_exact(acc[mi][ni][0] + eb1[e*1024 + c0]));
            g_h[(size_t)r0*1024 + c1] = rnd_tf(gelu_exact(acc[mi][ni][1] + eb1[e*1024 + c1]));
            g_h[(size_t)r1*1024 + c0] = rnd_tf(gelu_exact(acc[mi][ni][2] + eb1[e*1024 + c0]));
            g_h[(size_t)r1*1024 + c1] = rnd_tf(gelu_exact(acc[mi][ni][3] + eb1[e*1024 + c1]));
        }
}

__global__ void __launch_bounds__(NTHREADS, 2)
k_moe2(const float* __restrict__ eW2, const float* __restrict__ eb2) {
    int m0 = blockIdx.y * BM;
    if (m0 >= g_padoff[E_NUM]) return;
    extern __shared__ float sm[];
    int e = tile_expert(m0);
    const float* W2 = eW2 + (size_t)e * 1024 * 256;
    float acc[4][4][4] = {};
    int n0 = blockIdx.x * BN;
    gemm_tf32<false, true>(acc, g_h, 1024, 1024, W2, 256, m0, n0, nullptr, sm);
    FRAG_IDX
    #pragma unroll
    for (int mi = 0; mi < 4; mi++)
        #pragma unroll
        for (int ni = 0; ni < 4; ni++) {
            int s0 = m0 + mw + mi*16 + g, s1 = s0 + 8;
            int c0 = n0 + nw + ni*8 + t4*2, c1 = c0 + 1;
            int r0 = g_perm[s0], r1 = g_perm[s1];
            if (r0 >= 0) {
                float gate = g_gate[r0];
                g_zf[(size_t)r0*256 + c0] = rnd_tf(g_z[(size_t)r0*256 + c0] + gate*(acc[mi][ni][0] + eb2[e*256 + c0]));
                g_zf[(size_t)r0*256 + c1] = rnd_tf(g_z[(size_t)r0*256 + c1] + gate*(acc[mi][ni][1] + eb2[e*256 + c1]));
            }
            if (r1 >= 0) {
                float gate = g_gate[r1];
                g_zf[(size_t)r1*256 + c0] = rnd_tf(g_z[(size_t)r1*256 + c0] + gate*(acc[mi][ni][2] + eb2[e*256 + c0]));
                g_zf[(size_t)r1*256 + c1] = rnd_tf(g_z[(size_t)r1*256 + c1] + gate*(acc[mi][ni][3] + eb2[e*256 + c1]));
            }
        }
}

__global__ void __launch_bounds__(NTHREADS, 2)
k_tpre(const float* __restrict__ gdW1, const float* __restrict__ b) {
    extern __shared__ float sm[];
    float acc[4][4][4] = {};
    int m0 = blockIdx.y * BM, n0 = blockIdx.x * BN;
    gemm_tf32<false, true>(acc, g_zf, 256, 256, gdW1, 256, m0, n0, nullptr, sm);
    FRAG_IDX
    #pragma unroll
    for (int mi = 0; mi < 4; mi++)
        #pragma unroll
        for (int ni = 0; ni < 4; ni++) {
            int r0 = m0 + mw + mi*16 + g, r1 = r0 + 8;
            int c0 = n0 + nw + ni*8 + t4*2, c1 = c0 + 1;
            g_tpre[(size_t)r0*256 + c0] = acc[mi][ni][0] + b[c0];
            g_tpre[(size_t)r0*256 + c1] = acc[mi][ni][1] + b[c1];
            g_tpre[(size_t)r1*256 + c0] = acc[mi][ni][2] + b[c0];
            g_tpre[(size_t)r1*256 + c1] = acc[mi][ni][3] + b[c1];
        }
}

__global__ void k_ln(const float* __restrict__ gam, const float* __restrict__ beta) {
    int w = threadIdx.x >> 5, lane = threadIdx.x & 31;
    int row = blockIdx.x * 8 + w;
    float v[8]; float s = 0.f;
    #pragma unroll
    for (int i = 0; i < 8; i++) {
        v[i] = g_tpre[(size_t)row*256 + lane + 32*i];
        s += v[i];
    }
    #pragma unroll
    for (int off = 16; off; off >>= 1) s += __shfl_xor_sync(0xffffffffu, s, off);
    float mean = s * (1.f/256.f);
    float s2 = 0.f;
    #pragma unroll
    for (int i = 0; i < 8; i++) { float d = v[i] - mean; s2 = fmaf(d, d, s2); }
    #pragma unroll
    for (int off = 16; off; off >>= 1) s2 += __shfl_xor_sync(0xffffffffu, s2, off);
    float rs = rsqrtf(s2 * (1.f/256.f) + 1e-5f);
    #pragma unroll
    for (int i = 0; i < 8; i++) {
        int k = lane + 32*i;
        g_t[(size_t)row*256 + k] = rnd_tf(gelu_exact(gam[k] * (v[i] - mean) * rs + beta[k]));
    }
}

// gd2 with smem-staged, fully coalesced epilogue (R12 win)
__global__ void __launch_bounds__(NTHREADS, 2)
k_gd2(const float* __restrict__ gdW2, const float* __restrict__ b2,
      const float* __restrict__ lib, float* __restrict__ out) {
    extern __shared__ float sm[];
    float acc[4][4][4] = {};
    int m0 = blockIdx.y * BM, n0 = blockIdx.x * BN;
    gemm_tf32<false, true>(acc, g_t, 256, 256, gdW2, N_GD2, m0, n0, nullptr, sm);
    FRAG_IDX
    float* es = sm;
    #pragma unroll
    for (int mi = 0; mi < 4; mi++)
        #pragma unroll
        for (int ni = 0; ni < 4; ni++) {
            int r0 = mw + mi*16 + g, r1 = r0 + 8;
            int c0 = nw + ni*8 + t4*2, c1 = c0 + 1;
            es[r0*ES_STRIDE + c0] = acc[mi][ni][0];
            es[r0*ES_STRIDE + c1] = acc[mi][ni][1];
            es[r1*ES_STRIDE + c0] = acc[mi][ni][2];
            es[r1*ES_STRIDE + c1] = acc[mi][ni][3];
        }
    __syncthreads();
    const size_t THETA_OFF = (size_t)B_ROWS * G_NUM;
    int gbase = n0 >> 1;
    for (int r = warp; r < BM; r += 8) {
        int row = m0 + r;
        float lb = lib[row];
        #pragma unroll
        for (int j = 0; j < 2; j++) {
            int gcol = j*32 + lane;
            int col0 = 2*gcol, col1 = col0 + 1;
            if (n0 + col0 < N_GD2) {
                float v = es[r*ES_STRIDE + col0] + b2[n0 + col0];
                float sp = (v > 20.f) ? v : log1pf(expf(v));
                out[(size_t)row*G_NUM + gbase + gcol] = sp * lb + 1e-6f;
            }
            if (n0 + col1 < N_GD2) {
                float v = es[r*ES_STRIDE + col1] + b2[n0 + col1];
                float sp = (v > 20.f) ? v : log1pf(expf(v));
                out[THETA_OFF + (size_t)row*G_NUM + gbase + gcol] = sp + 1e-6f;
            }
        }
    }
}

// merged align + func hidden: N=192 packed weights (pre-rounded)
__global__ void __launch_bounds__(NTHREADS, 2)
k_apfh(const float* __restrict__ apb, const float* __restrict__ fhb) {
    extern __shared__ float sm[];
    float acc[4][4][4] = {};
    int m0 = blockIdx.y * BM, n0 = blockIdx.x * BN;
    gemm_tf32<false, false>(acc, g_zf, 256, 256, g_w_apfh, 192, m0, n0, nullptr, sm);
    FRAG_IDX
    #pragma unroll
    for (int mi = 0; mi < 4; mi++)
        #pragma unroll
        for (int ni = 0; ni < 4; ni++) {
            int r0 = m0 + mw + mi*16 + g, r1 = r0 + 8;
            int c0 = n0 + nw + ni*8 + t4*2, c1 = c0 + 1;
            #pragma unroll
            for (int q = 0; q < 4; q++) {
                int r = (q & 2) ? r1 : r0;
                int c = (q & 1) ? c1 : c0;
                float v = acc[mi][ni][q];
                if (c < 128)
                    g_a1[(size_t)r*128 + c] = gelu_exact(v + apb[c]);
                else if (c < 192)
                    g_f1[(size_t)r*64 + (c - 128)] = gelu_exact(v + fhb[c - 128]);
            }
        }
}

__global__ void k_ap2(const float* __restrict__ W2, const float* __restrict__ b2,
                      float* __restrict__ out) {
    __shared__ float Ws[128*SCVI_];
    __shared__ float bs[SCVI_];
    for (int i = threadIdx.x; i < 128*SCVI_; i += 256) Ws[i] = W2[i];
    if (threadIdx.x < SCVI_) bs[threadIdx.x] = b2[threadIdx.x];
    __syncthreads();
    int w = threadIdx.x >> 5, lane = threadIdx.x & 31;
    int row = blockIdx.x * 8 + w;
    float a[4];
    #pragma unroll
    for (int i = 0; i < 4; i++) a[i] = g_a1[(size_t)row*128 + lane + 32*i];
    const size_t ALIGN_OFF = 2ull * B_ROWS * G_NUM + B_ROWS;
    for (int c = 0; c < SCVI_; c++) {
        float s = 0.f;
        #pragma unroll
        for (int i = 0; i < 4; i++) s = fmaf(a[i], Ws[(lane + 32*i)*SCVI_ + c], s);
        #pragma unroll
        for (int off = 16; off; off >>= 1) s += __shfl_down_sync(0xffffffffu, s, off);
        if (lane == 0) out[ALIGN_OFF + (size_t)row*SCVI_ + c] = s + bs[c];
    }
}

__global__ void k_fh2(const float* __restrict__ W2, const float* __restrict__ b2,
                      float* __restrict__ out) {
    int w = threadIdx.x >> 5, lane = threadIdx.x & 31;
    int row = blockIdx.x * 8 + w;
    float v = g_f1[(size_t)row*64 + lane] * W2[lane]
            + g_f1[(size_t)row*64 + lane + 32] * W2[lane + 32];
    #pragma unroll
    for (int off = 16; off; off >>= 1) v += __shfl_down_sync(0xffffffffu, v, off);
    if (lane == 0) {
        const size_t FUNC_OFF = 2ull * B_ROWS * G_NUM;
        out[FUNC_OFF + row] = 1.f / (1.f + expf(-(v + b2[0])));
    }
}

// ---------------- launch ----------------
extern "C" void kernel_launch(void* const* d_in, const int* in_sizes, int n_in,
                              void* d_out, int out_size) {
    const float* vis   = (const float*)d_in[0];
    const float* pos   = (const float*)d_in[1];
    const float* grad  = (const float*)d_in[2];
    const float* lib   = (const float*)d_in[3];
    const float* fB    = (const float*)d_in[4];
    const float* img_W = (const float*)d_in[5];
    const float* img_b = (const float*)d_in[6];
    const float* pos_W = (const float*)d_in[7];
    const float* pos_b = (const float*)d_in[8];
    const float* rW    = (const float*)d_in[9];
    const float* rb    = (const float*)d_in[10];
    const float* eW1   = (const float*)d_in[11];
    const float* eb1   = (const float*)d_in[12];
    const float* eW2   = (const float*)d_in[13];
    const float* eb2   = (const float*)d_in[14];
    const float* gdW1  = (const float*)d_in[15];
    const float* gdb1  = (const float*)d_in[16];
    const float* gdg   = (const float*)d_in[17];
    const float* gdbe  = (const float*)d_in[18];
    const float* gdW2  = (const float*)d_in[19];
    const float* gdb2  = (const float*)d_in[20];
    const float* apW1  = (const float*)d_in[21];
    const float* apb1  = (const float*)d_in[22];
    const float* apW2  = (const float*)d_in[23];
    const float* apb2  = (const float*)d_in[24];
    const float* fhW1  = (const float*)d_in[25];
    const float* fhb1  = (const float*)d_in[26];
    const float* fhW2  = (const float*)d_in[27];
    const float* fhb2  = (const float*)d_in[28];
    float* out = (float*)d_out;

    static const int SM = SMEM_BYTES;
    cudaFuncSetAttribute(k_gemm_z, cudaFuncAttributeMaxDynamicSharedMemorySize, SM);
    cudaFuncSetAttribute(k_moe1,   cudaFuncAttributeMaxDynamicSharedMemorySize, SM);
    cudaFuncSetAttribute(k_moe2,   cudaFuncAttributeMaxDynamicSharedMemorySize, SM);
    cudaFuncSetAttribute(k_tpre,   cudaFuncAttributeMaxDynamicSharedMemorySize, SM);
    cudaFuncSetAttribute(k_gd2,    cudaFuncAttributeMaxDynamicSharedMemorySize, SM);
    cudaFuncSetAttribute(k_apfh,   cudaFuncAttributeMaxDynamicSharedMemorySize, SM);

    k_round_apfh<<<(12288 + 255)/256, 256>>>(apW1, fhW1);

    k_four   <<<B_ROWS/8, 256>>>(pos, fB);
    k_gemm_z <<<dim3(2, B_ROWS/BM), NTHREADS, SM>>>(vis, pos_W, img_W, img_b, pos_b);
    k_router <<<B_ROWS/8, 256>>>(grad, rW, rb);
    k_offsets<<<1,1>>>();
    k_scatter<<<B_ROWS/256, 256>>>();
    k_moe1   <<<dim3(8, MAX_TILES), NTHREADS, SM>>>(eW1, eb1);
    k_moe2   <<<dim3(2, MAX_TILES), NTHREADS, SM>>>(eW2, eb2);
    k_tpre   <<<dim3(2, B_ROWS/BM), NTHREADS, SM>>>(gdW1, gdb1);
    k_ln     <<<B_ROWS/8, 256>>>(gdg, gdbe);
    k_gd2    <<<dim3((N_GD2 + BN - 1)/BN, B_ROWS/BM), NTHREADS, SM>>>(gdW2, gdb2, lib, out);
    k_apfh   <<<dim3(2, B_ROWS/BM), NTHREADS, SM>>>(apb1, fhb1);
    k_ap2    <<<B_ROWS/8, 256>>>(apW2, apb2, out);
    k_fh2    <<<B_ROWS/8, 256>>>(fhW2, fhb2, out);
}

// round 14
// speedup vs baseline: 1.3237x; 1.3237x over previous
#include <cuda_runtime.h>
#include <cuda_fp16.h>
#include <cstdint>
#include <math.h>

// ---------------- problem dims ----------------
#define B_ROWS 16384
#define D_VIS  1024
#define D_H    256
#define E_NUM  4
#define G_NUM  5000
#define MAP_   128
#define SCVI_  30
#define N_GD2  (G_NUM*2)
#define NT_PAD 10112            // 79 tiles * 128

// ---------------- tf32 mma.sync GEMM tile config (R12) ----------------
#define BM 128
#define BN 128
#define BK 32
#define STAGES 3
#define NTHREADS 256
#define AS_STRIDE 40
#define BS_STRIDE 132
#define AS_SIZE (BM*AS_STRIDE)
#define BS_SIZE (BK*BS_STRIDE)
#define STAGE_FLOATS (AS_SIZE + BS_SIZE)
#define SMEM_BYTES (STAGES*STAGE_FLOATS*4)
#define MAX_TILES 132
#define ES_STRIDE 132

// ---------------- fp16 gd2 GEMM config ----------------
#define HBK 64                   // k-halfs per tile
#define H_AS 36                  // words per 64-half row (32 data + 4 pad)
#define H_HALF (128*H_AS)        // words per operand tile
#define H_STAGE (2*H_HALF)       // 9216 words
#define H_SMEM (3*H_STAGE*4)     // 110592 B

// ---------------- scratch ----------------
__device__ float g_four[(size_t)B_ROWS*2*MAP_];
__device__ float g_z   [(size_t)B_ROWS*D_H];
__device__ float g_zr  [(size_t)B_ROWS*D_H];
__device__ float g_zf  [(size_t)B_ROWS*D_H];
__device__ float g_tpre[(size_t)B_ROWS*D_H];
__device__ __half g_t_h[(size_t)B_ROWS*D_H];
__device__ float g_a1  [(size_t)B_ROWS*128];
__device__ float g_f1  [(size_t)B_ROWS*64];
__device__ float g_h   [(size_t)MAX_TILES*BM*1024];
__device__ int   g_eid [B_ROWS];
__device__ float g_gate[B_ROWS];
__device__ int   g_perm[MAX_TILES*BM];
__device__ int   g_counts[E_NUM];
__device__ int   g_cursor[E_NUM];
__device__ int   g_padoff[E_NUM+1];
// pre-rounded weights (tf32 path)
__device__ float g_w_pos[256*256];
__device__ float g_w_img[1024*256];
__device__ float g_w_e1 [E_NUM*256*1024];
__device__ float g_w_e2 [E_NUM*1024*256];
__device__ float g_w_gd1[256*256];
__device__ float g_w_apfh[256*192];
// gd2 weight: transposed + fp16, [NT_PAD][256]
__device__ __half g_wt[(size_t)NT_PAD*256];

// ---------------- helpers ----------------
__device__ __forceinline__ float gelu_exact(float x) {
    return 0.5f * x * (1.0f + erff(x * 0.70710678118654752440f));
}
__device__ __forceinline__ uint32_t f2tf(float f) {
    uint32_t o; asm("cvt.rna.tf32.f32 %0, %1;" : "=r"(o) : "f"(f)); return o;
}
__device__ __forceinline__ float rnd_tf(float f) { return __uint_as_float(f2tf(f)); }

__device__ __forceinline__ void mma8(float* c, const uint32_t* a, const uint32_t* b) {
    asm volatile("mma.sync.aligned.m16n8k8.row.col.f32.tf32.tf32.f32 "
        "{%0,%1,%2,%3}, {%4,%5,%6,%7}, {%8,%9}, {%0,%1,%2,%3};"
        : "+f"(c[0]), "+f"(c[1]), "+f"(c[2]), "+f"(c[3])
        : "r"(a[0]), "r"(a[1]), "r"(a[2]), "r"(a[3]), "r"(b[0]), "r"(b[1]));
}
__device__ __forceinline__ void mma16h(float* c, const uint32_t* a, const uint32_t* b) {
    asm volatile("mma.sync.aligned.m16n8k16.row.col.f32.f16.f16.f32 "
        "{%0,%1,%2,%3}, {%4,%5,%6,%7}, {%8,%9}, {%0,%1,%2,%3};"
        : "+f"(c[0]), "+f"(c[1]), "+f"(c[2]), "+f"(c[3])
        : "r"(a[0]), "r"(a[1]), "r"(a[2]), "r"(a[3]), "r"(b[0]), "r"(b[1]));
}
__device__ __forceinline__ void cp_async16(float* dst_smem, const float* src, int src_bytes) {
    uint32_t d = (uint32_t)__cvta_generic_to_shared(dst_smem);
    asm volatile("cp.async.cg.shared.global [%0], [%1], 16, %2;\n"
                 :: "r"(d), "l"(src), "r"(src_bytes));
}
__device__ __forceinline__ void cp16f(float* dst_smem, const float* src) {
    uint32_t d = (uint32_t)__cvta_generic_to_shared(dst_smem);
    asm volatile("cp.async.cg.shared.global [%0], [%1], 16;\n" :: "r"(d), "l"(src));
}
__device__ __forceinline__ void cp_commit() { asm volatile("cp.async.commit_group;\n"); }
template<int N> __device__ __forceinline__ void cp_wait() {
    asm volatile("cp.async.wait_group %0;\n" :: "n"(N));
}

// ---------------- weight pre-round (gd2 excluded; handled by transpose) ----------------
#define N4_POS 16384
#define N4_IMG 65536
#define N4_E1  262144
#define N4_E2  262144
#define N4_GD1 16384
#define N4_AP1 8192
#define N4_FH1 4096
#define RC0 (N4_POS)
#define RC1 (RC0+N4_IMG)
#define RC2 (RC1+N4_E1)
#define RC3 (RC2+N4_E2)
#define RC4 (RC3+N4_GD1)
#define RC5 (RC4+N4_AP1)
#define RC6 (RC5+N4_FH1)

__global__ void k_round_all(const float* __restrict__ pos_W, const float* __restrict__ img_W,
                            const float* __restrict__ eW1,   const float* __restrict__ eW2,
                            const float* __restrict__ gdW1,
                            const float* __restrict__ apW1,  const float* __restrict__ fhW1) {
    int i = blockIdx.x * blockDim.x + threadIdx.x;
    if (i >= RC6) return;
    const float* src; float* dst; int off; int dsti;
    if      (i < RC0) { src = pos_W; dst = g_w_pos; off = i;       dsti = off; }
    else if (i < RC1) { src = img_W; dst = g_w_img; off = i - RC0; dsti = off; }
    else if (i < RC2) { src = eW1;   dst = g_w_e1;  off = i - RC1; dsti = off; }
    else if (i < RC3) { src = eW2;   dst = g_w_e2;  off = i - RC2; dsti = off; }
    else if (i < RC4) { src = gdW1;  dst = g_w_gd1; off = i - RC3; dsti = off; }
    else if (i < RC5) {
        src = apW1; dst = g_w_apfh; off = i - RC4;
        int row = off >> 5, c4 = off & 31;
        dsti = row * 48 + c4;
    }
    else {
        src = fhW1; dst = g_w_apfh; off = i - RC5;
        int row = off >> 4, c4 = off & 15;
        dsti = row * 48 + 32 + c4;
    }
    float4 v = ((const float4*)src)[off];
    v.x = rnd_tf(v.x); v.y = rnd_tf(v.y); v.z = rnd_tf(v.z); v.w = rnd_tf(v.w);
    ((float4*)dst)[dsti] = v;
}

// transpose + fp16-convert gd_W2 [256, N_GD2] -> g_wt [NT_PAD, 256]
__global__ void k_tr_gd2(const float* __restrict__ W) {
    __shared__ float t[32][33];
    int n0 = blockIdx.x * 32, k0 = blockIdx.y * 32;
    int tx = threadIdx.x & 31, ty = threadIdx.x >> 5;
    #pragma unroll
    for (int i = ty; i < 32; i += 8) {
        int n = n0 + tx;
        t[i][tx] = (n < N_GD2) ? W[(size_t)(k0 + i) * N_GD2 + n] : 0.f;
    }
    __syncthreads();
    #pragma unroll
    for (int i = ty; i < 32; i += 8)
        g_wt[(size_t)(n0 + i) * 256 + k0 + tx] = __float2half_rn(t[tx][i]);
}

// ---------------- tf32 GEMM machinery (exact R12) ----------------
__device__ __forceinline__ void issue_tile(
    float* stage,
    const float* __restrict__ A, int lda,
    const float* __restrict__ W, int N,
    int m0, int n0, int k0, const int* __restrict__ perm)
{
    float* As = stage;
    float* Bs = stage + AS_SIZE;
    const int tid = threadIdx.x;
    int ar = tid >> 1;
    int ac = (tid & 1) * 16;
    if (perm) {
        int rowg = perm[m0 + ar];
        const float* srcA = A + (size_t)(rowg < 0 ? 0 : rowg) * lda + k0 + ac;
        int szA = (rowg >= 0) ? 16 : 0;
        #pragma unroll
        for (int i = 0; i < 4; i++)
            cp_async16(As + ar*AS_STRIDE + ac + i*4, srcA + i*4, szA);
    } else {
        const float* srcA = A + (size_t)(m0 + ar) * lda + k0 + ac;
        #pragma unroll
        for (int i = 0; i < 4; i++)
            cp16f(As + ar*AS_STRIDE + ac + i*4, srcA + i*4);
    }
    int br = tid >> 3;
    int bc = (tid & 7) * 16;
    const float* srcB = W + (size_t)(k0 + br) * N + n0 + bc;
    if (n0 + BN <= N) {
        #pragma unroll
        for (int i = 0; i < 4; i++)
            cp16f(Bs + br*BS_STRIDE + bc + i*4, srcB + i*4);
    } else {
        #pragma unroll
        for (int i = 0; i < 4; i++) {
            int col = n0 + bc + i*4;
            int bytes = (N - col) * 4;
            bytes = bytes < 0 ? 0 : (bytes > 16 ? 16 : bytes);
            cp_async16(Bs + br*BS_STRIDE + bc + i*4, bytes > 0 ? (srcB + i*4) : W, bytes);
        }
    }
}

template<bool CVTA>
__device__ __forceinline__ void gemm_tf32(
    float acc[4][4][4],
    const float* __restrict__ A, int lda, int K,
    const float* __restrict__ W, int N,
    int m0, int n0, const int* __restrict__ perm, float* sm)
{
    const int KT = K >> 5;
    #pragma unroll
    for (int s = 0; s < STAGES-1; s++) {
        if (s < KT) issue_tile(sm + s*STAGE_FLOATS, A, lda, W, N, m0, n0, s*BK, perm);
        cp_commit();
    }
    cp_wait<STAGES-2>();
    __syncthreads();

    const int warp = threadIdx.x >> 5, lane = threadIdx.x & 31;
    const int mw = (warp >> 2) * 64, nw = (warp & 3) * 32;
    const int g = lane >> 2, t4 = lane & 3;

    for (int kt = 0; kt < KT; kt++) {
        const float* Asf = sm + (kt%STAGES)*STAGE_FLOATS;
        const uint32_t* As = (const uint32_t*)Asf;
        const uint32_t* Bs = (const uint32_t*)(Asf + AS_SIZE);
        #pragma unroll
        for (int ks = 0; ks < BK/8; ks++) {
            const int k0s = ks * 8;
            uint32_t af[4][4], bf[4][2];
            #pragma unroll
            for (int mi = 0; mi < 4; mi++) {
                int r = mw + mi*16 + g;
                uint2 pa = *(const uint2*)(As + (r  )*AS_STRIDE + k0s + 2*t4);
                uint2 pb = *(const uint2*)(As + (r+8)*AS_STRIDE + k0s + 2*t4);
                if (CVTA) {
                    af[mi][0] = f2tf(__uint_as_float(pa.x));
                    af[mi][2] = f2tf(__uint_as_float(pa.y));
                    af[mi][1] = f2tf(__uint_as_float(pb.x));
                    af[mi][3] = f2tf(__uint_as_float(pb.y));
                } else {
                    af[mi][0] = pa.x; af[mi][2] = pa.y;
                    af[mi][1] = pb.x; af[mi][3] = pb.y;
                }
            }
            #pragma unroll
            for (int ni = 0; ni < 4; ni++) {
                int c = nw + ni*8 + g;
                bf[ni][0] = Bs[(k0s + 2*t4    )*BS_STRIDE + c];
                bf[ni][1] = Bs[(k0s + 2*t4 + 1)*BS_STRIDE + c];
            }
            #pragma unroll
            for (int mi = 0; mi < 4; mi++)
                #pragma unroll
                for (int ni = 0; ni < 4; ni++)
                    mma8(acc[mi][ni], af[mi], bf[ni]);
        }
        int pre = kt + STAGES - 1;
        if (pre < KT) issue_tile(sm + (pre%STAGES)*STAGE_FLOATS, A, lda, W, N, m0, n0, pre*BK, perm);
        cp_commit();
        cp_wait<STAGES-2>();
        __syncthreads();
    }
}

#define FRAG_IDX \
    const int warp = threadIdx.x >> 5, lane = threadIdx.x & 31; \
    const int mw = (warp >> 2) * 64, nw = (warp & 3) * 32; \
    const int g = lane >> 2, t4 = lane & 3;

// ---------------- fp16 gd2 GEMM machinery ----------------
// A = g_t_h [M][256] halfs (k-contiguous); Wt = g_wt [n][256] halfs.
__device__ __forceinline__ void issue_tile_h(
    float* stage, const __half* __restrict__ A, const __half* __restrict__ Wt,
    int m0, int n0, int k0)
{
    float* As = stage;
    float* Bs = stage + H_HALF;
    const int tid = threadIdx.x;
    int r = tid >> 1;
    int jb = (tid & 1) * 4;
    const __half* srcA = A  + (size_t)(m0 + r)*256 + k0;
    const __half* srcB = Wt + (size_t)(n0 + r)*256 + k0;
    #pragma unroll
    for (int i = 0; i < 4; i++) {
        int j = jb + i;
        cp16f(As + r*H_AS + j*4, (const float*)(srcA + j*8));
        cp16f(Bs + r*H_AS + j*4, (const float*)(srcB + j*8));
    }
}

__device__ __forceinline__ void gemm_f16_gd2(
    float acc[4][4][4], const __half* __restrict__ A, const __half* __restrict__ Wt,
    int m0, int n0, float* sm)
{
    const int KT = 256 / HBK;   // 4
    #pragma unroll
    for (int s = 0; s < STAGES-1; s++) {
        issue_tile_h(sm + s*H_STAGE, A, Wt, m0, n0, s*HBK);
        cp_commit();
    }
    cp_wait<STAGES-2>();
    __syncthreads();

    const int warp = threadIdx.x >> 5, lane = threadIdx.x & 31;
    const int mw = (warp >> 2) * 64, nw = (warp & 3) * 32;
    const int g = lane >> 2, t4 = lane & 3;

    for (int kt = 0; kt < KT; kt++) {
        const uint32_t* As = (const uint32_t*)(sm + (kt%STAGES)*H_STAGE);
        const uint32_t* Bs = As + H_HALF;
        #pragma unroll
        for (int s = 0; s < HBK/16; s++) {
            const int w0 = s*8 + t4;
            uint32_t af[4][4], bf[4][2];
            #pragma unroll
            for (int mi = 0; mi < 4; mi++) {
                int r = mw + mi*16 + g;
                af[mi][0] = As[(r  )*H_AS + w0];
                af[mi][1] = As[(r+8)*H_AS + w0];
                af[mi][2] = As[(r  )*H_AS + w0 + 4];
                af[mi][3] = As[(r+8)*H_AS + w0 + 4];
            }
            #pragma unroll
            for (int ni = 0; ni < 4; ni++) {
                int c = nw + ni*8 + g;
                bf[ni][0] = Bs[c*H_AS + w0];
                bf[ni][1] = Bs[c*H_AS + w0 + 4];
            }
            #pragma unroll
            for (int mi = 0; mi < 4; mi++)
                #pragma unroll
                for (int ni = 0; ni < 4; ni++)
                    mma16h(acc[mi][ni], af[mi], bf[ni]);
        }
        int pre = kt + STAGES - 1;
        if (pre < KT) issue_tile_h(sm + (pre%STAGES)*H_STAGE, A, Wt, m0, n0, pre*HBK);
        cp_commit();
        cp_wait<STAGES-2>();
        __syncthreads();
    }
}

// ---------------- stage kernels ----------------
__global__ void k_four(const float* __restrict__ pos, const float* __restrict__ fB) {
    int gtid = blockIdx.x * 256 + threadIdx.x;
    if (gtid < MAX_TILES*BM) g_perm[gtid] = -1;
    if (gtid < E_NUM) { g_counts[gtid] = 0; g_cursor[gtid] = 0; }

    int w = threadIdx.x >> 5, lane = threadIdx.x & 31;
    int row = blockIdx.x * 8 + w;
    float p0 = pos[row*3+0], p1 = pos[row*3+1], p2 = pos[row*3+2];
    #pragma unroll
    for (int i = 0; i < 4; i++) {
        int c = lane + 32*i;
        float xp = 6.283185307179586477f * (p0*fB[c] + p1*fB[MAP_+c] + p2*fB[2*MAP_+c]);
        float s, co;
        sincosf(xp, &s, &co);
        g_four[(size_t)row*256 + c]       = rnd_tf(s);
        g_four[(size_t)row*256 + 128 + c] = rnd_tf(co);
    }
}

__global__ void __launch_bounds__(NTHREADS, 2)
k_gemm_z(const float* __restrict__ vis,
         const float* __restrict__ img_b, const float* __restrict__ pos_b) {
    extern __shared__ float sm[];
    float acc[4][4][4] = {};
    int m0 = blockIdx.y * BM, n0 = blockIdx.x * BN;
    FRAG_IDX
    gemm_tf32<false>(acc, g_four, 256, 256, g_w_pos, 256, m0, n0, nullptr, sm);
    #pragma unroll
    for (int mi = 0; mi < 4; mi++)
        #pragma unroll
        for (int ni = 0; ni < 4; ni++) {
            int c0 = n0 + nw + ni*8 + t4*2;
            acc[mi][ni][0] = gelu_exact(acc[mi][ni][0] + pos_b[c0]);
            acc[mi][ni][1] = gelu_exact(acc[mi][ni][1] + pos_b[c0+1]);
            acc[mi][ni][2] = gelu_exact(acc[mi][ni][2] + pos_b[c0]);
            acc[mi][ni][3] = gelu_exact(acc[mi][ni][3] + pos_b[c0+1]);
        }
    gemm_tf32<true>(acc, vis, D_VIS, D_VIS, g_w_img, 256, m0, n0, nullptr, sm);
    #pragma unroll
    for (int mi = 0; mi < 4; mi++)
        #pragma unroll
        for (int ni = 0; ni < 4; ni++) {
            int r0 = m0 + mw + mi*16 + g, r1 = r0 + 8;
            int c0 = n0 + nw + ni*8 + t4*2, c1 = c0 + 1;
            float v00 = acc[mi][ni][0] + img_b[c0];
            float v01 = acc[mi][ni][1] + img_b[c1];
            float v10 = acc[mi][ni][2] + img_b[c0];
            float v11 = acc[mi][ni][3] + img_b[c1];
            g_z [(size_t)r0*256 + c0] = v00;  g_zr[(size_t)r0*256 + c0] = rnd_tf(v00);
            g_z [(size_t)r0*256 + c1] = v01;  g_zr[(size_t)r0*256 + c1] = rnd_tf(v01);
            g_z [(size_t)r1*256 + c0] = v10;  g_zr[(size_t)r1*256 + c0] = rnd_tf(v10);
            g_z [(size_t)r1*256 + c1] = v11;  g_zr[(size_t)r1*256 + c1] = rnd_tf(v11);
        }
}

__global__ void k_router(const float* __restrict__ grad,
                         const float* __restrict__ rW, const float* __restrict__ rb) {
    int w = threadIdx.x >> 5, lane = threadIdx.x & 31;
    int row = blockIdx.x * 8 + w;
    float4 s = make_float4(0.f,0.f,0.f,0.f);
    #pragma unroll
    for (int i = 0; i < 8; i++) {
        int k = lane + 32*i;
        float zv = g_z[(size_t)row*256 + k];
        float4 wv = *(const float4*)(rW + k*4);
        s.x = fmaf(zv, wv.x, s.x); s.y = fmaf(zv, wv.y, s.y);
        s.z = fmaf(zv, wv.z, s.z); s.w = fmaf(zv, wv.w, s.w);
    }
    #pragma unroll
    for (int off = 16; off; off >>= 1) {
        s.x += __shfl_down_sync(0xffffffffu, s.x, off);
        s.y += __shfl_down_sync(0xffffffffu, s.y, off);
        s.z += __shfl_down_sync(0xffffffffu, s.z, off);
        s.w += __shfl_down_sync(0xffffffffu, s.w, off);
    }
    if (lane == 0) {
        float gv = grad[row];
        float4 wg = *(const float4*)(rW + 256*4);
        float l0 = s.x + gv*wg.x + rb[0];
        float l1 = s.y + gv*wg.y + rb[1];
        float l2 = s.z + gv*wg.z + rb[2];
        float l3 = s.w + gv*wg.w + rb[3];
        float m = l0; int am = 0;
        if (l1 > m) { m = l1; am = 1; }
        if (l2 > m) { m = l2; am = 2; }
        if (l3 > m) { m = l3; am = 3; }
        float sum = expf(l0-m) + expf(l1-m) + expf(l2-m) + expf(l3-m);
        g_eid[row]  = am;
        g_gate[row] = 1.0f / sum;
        atomicAdd(&g_counts[am], 1);
    }
}

__global__ void k_offsets() {
    int off = 0;
    for (int e = 0; e < E_NUM; e++) {
        g_padoff[e] = off;
        off += ((g_counts[e] + BM - 1) / BM) * BM;
    }
    g_padoff[E_NUM] = off;
}

__global__ void k_scatter() {
    int row = blockIdx.x * 256 + threadIdx.x;
    int e = g_eid[row];
    int slot = g_padoff[e] + atomicAdd(&g_cursor[e], 1);
    g_perm[slot] = row;
}

__device__ __forceinline__ int tile_expert(int m0) {
    int e = 0;
    while (e < E_NUM-1 && m0 >= g_padoff[e+1]) e++;
    return e;
}

__global__ void __launch_bounds__(NTHREADS, 2)
k_moe1(const float* __restrict__ eb1) {
    int m0 = blockIdx.y * BM;
    if (m0 >= g_padoff[E_NUM]) return;
    extern __shared__ float sm[];
    int e = tile_expert(m0);
    const float* W1 = g_w_e1 + (size_t)e * 256 * 1024;
    float acc[4][4][4] = {};
    int n0 = blockIdx.x * BN;
    gemm_tf32<false>(acc, g_zr, 256, 256, W1, 1024, m0, n0, g_perm, sm);
    FRAG_IDX
    #pragma unroll
    for (int mi = 0; mi < 4; mi++)
        #pragma unroll
        for (int ni = 0; ni < 4; ni++) {
            int r0 = m0 + mw + mi*16 + g, r1 = r0 + 8;
            int c0 = n0 + nw + ni*8 + t4*2, c1 = c0 + 1;
            g_h[(size_t)r0*1024 + c0] = rnd_tf(gelu_exact(acc[mi][ni][0] + eb1[e*1024 + c0]));
            g_h[(size_t)r0*1024 + c1] = rnd_tf(gelu_exact(acc[mi][ni][1] + eb1[e*1024 + c1]));
            g_h[(size_t)r1*1024 + c0] = rnd_tf(gelu_exact(acc[mi][ni][2] + eb1[e*1024 + c0]));
            g_h[(size_t)r1*1024 + c1] = rnd_tf(gelu_exact(acc[mi][ni][3] + eb1[e*1024 + c1]));
        }
}

__global__ void __launch_bounds__(NTHREADS, 2)
k_moe2(const float* __restrict__ eb2) {
    int m0 = blockIdx.y * BM;
    if (m0 >= g_padoff[E_NUM]) return;
    extern __shared__ float sm[];
    int e = tile_expert(m0);
    const float* W2 = g_w_e2 + (size_t)e * 1024 * 256;
    float acc[4][4][4] = {};
    int n0 = blockIdx.x * BN;
    gemm_tf32<false>(acc, g_h, 1024, 1024, W2, 256, m0, n0, nullptr, sm);
    FRAG_IDX
    #pragma unroll
    for (int mi = 0; mi < 4; mi++)
        #pragma unroll
        for (int ni = 0; ni < 4; ni++) {
            int s0 = m0 + mw + mi*16 + g, s1 = s0 + 8;
            int c0 = n0 + nw + ni*8 + t4*2, c1 = c0 + 1;
            int r0 = g_perm[s0], r1 = g_perm[s1];
            if (r0 >= 0) {
                float gate = g_gate[r0];
                g_zf[(size_t)r0*256 + c0] = rnd_tf(g_z[(size_t)r0*256 + c0] + gate*(acc[mi][ni][0] + eb2[e*256 + c0]));
                g_zf[(size_t)r0*256 + c1] = rnd_tf(g_z[(size_t)r0*256 + c1] + gate*(acc[mi][ni][1] + eb2[e*256 + c1]));
            }
            if (r1 >= 0) {
                float gate = g_gate[r1];
                g_zf[(size_t)r1*256 + c0] = rnd_tf(g_z[(size_t)r1*256 + c0] + gate*(acc[mi][ni][2] + eb2[e*256 + c0]));
                g_zf[(size_t)r1*256 + c1] = rnd_tf(g_z[(size_t)r1*256 + c1] + gate*(acc[mi][ni][3] + eb2[e*256 + c1]));
            }
        }
}

__global__ void __launch_bounds__(NTHREADS, 2)
k_tpre(const float* __restrict__ b) {
    extern __shared__ float sm[];
    float acc[4][4][4] = {};
    int m0 = blockIdx.y * BM, n0 = blockIdx.x * BN;
    gemm_tf32<false>(acc, g_zf, 256, 256, g_w_gd1, 256, m0, n0, nullptr, sm);
    FRAG_IDX
    #pragma unroll
    for (int mi = 0; mi < 4; mi++)
        #pragma unroll
        for (int ni = 0; ni < 4; ni++) {
            int r0 = m0 + mw + mi*16 + g, r1 = r0 + 8;
            int c0 = n0 + nw + ni*8 + t4*2, c1 = c0 + 1;
            g_tpre[(size_t)r0*256 + c0] = acc[mi][ni][0] + b[c0];
            g_tpre[(size_t)r0*256 + c1] = acc[mi][ni][1] + b[c1];
            g_tpre[(size_t)r1*256 + c0] = acc[mi][ni][2] + b[c0];
            g_tpre[(size_t)r1*256 + c1] = acc[mi][ni][3] + b[c1];
        }
}

// LayerNorm + gelu -> fp16 output for gd2
__global__ void k_ln(const float* __restrict__ gam, const float* __restrict__ beta) {
    int w = threadIdx.x >> 5, lane = threadIdx.x & 31;
    int row = blockIdx.x * 8 + w;
    float v[8]; float s = 0.f;
    #pragma unroll
    for (int i = 0; i < 8; i++) {
        v[i] = g_tpre[(size_t)row*256 + lane + 32*i];
        s += v[i];
    }
    #pragma unroll
    for (int off = 16; off; off >>= 1) s += __shfl_xor_sync(0xffffffffu, s, off);
    float mean = s * (1.f/256.f);
    float s2 = 0.f;
    #pragma unroll
    for (int i = 0; i < 8; i++) { float d = v[i] - mean; s2 = fmaf(d, d, s2); }
    #pragma unroll
    for (int off = 16; off; off >>= 1) s2 += __shfl_xor_sync(0xffffffffu, s2, off);
    float rs = rsqrtf(s2 * (1.f/256.f) + 1e-5f);
    #pragma unroll
    for (int i = 0; i < 8; i++) {
        int k = lane + 32*i;
        g_t_h[(size_t)row*256 + k] = __float2half_rn(gelu_exact(gam[k] * (v[i] - mean) * rs + beta[k]));
    }
}

// fp16 gd2 with coalesced smem-staged epilogue (R12 epilogue)
__global__ void __launch_bounds__(NTHREADS, 2)
k_gd2(const float* __restrict__ b2,
      const float* __restrict__ lib, float* __restrict__ out) {
    extern __shared__ float sm[];
    float acc[4][4][4] = {};
    int m0 = blockIdx.y * BM, n0 = blockIdx.x * BN;
    gemm_f16_gd2(acc, g_t_h, g_wt, m0, n0, sm);
    FRAG_IDX
    float* es = sm;
    #pragma unroll
    for (int mi = 0; mi < 4; mi++)
        #pragma unroll
        for (int ni = 0; ni < 4; ni++) {
            int r0 = mw + mi*16 + g, r1 = r0 + 8;
            int c0 = nw + ni*8 + t4*2, c1 = c0 + 1;
            es[r0*ES_STRIDE + c0] = acc[mi][ni][0];
            es[r0*ES_STRIDE + c1] = acc[mi][ni][1];
            es[r1*ES_STRIDE + c0] = acc[mi][ni][2];
            es[r1*ES_STRIDE + c1] = acc[mi][ni][3];
        }
    __syncthreads();
    const size_t THETA_OFF = (size_t)B_ROWS * G_NUM;
    int gbase = n0 >> 1;
    for (int r = warp; r < BM; r += 8) {
        int row = m0 + r;
        float lb = lib[row];
        #pragma unroll
        for (int j = 0; j < 2; j++) {
            int gcol = j*32 + lane;
            int col0 = 2*gcol, col1 = col0 + 1;
            if (n0 + col0 < N_GD2) {
                float v = es[r*ES_STRIDE + col0] + b2[n0 + col0];
                float sp = (v > 20.f) ? v : log1pf(expf(v));
                out[(size_t)row*G_NUM + gbase + gcol] = sp * lb + 1e-6f;
            }
            if (n0 + col1 < N_GD2) {
                float v = es[r*ES_STRIDE + col1] + b2[n0 + col1];
                float sp = (v > 20.f) ? v : log1pf(expf(v));
                out[THETA_OFF + (size_t)row*G_NUM + gbase + gcol] = sp + 1e-6f;
            }
        }
    }
}

__global__ void __launch_bounds__(NTHREADS, 2)
k_apfh(const float* __restrict__ apb, const float* __restrict__ fhb) {
    extern __shared__ float sm[];
    float acc[4][4][4] = {};
    int m0 = blockIdx.y * BM, n0 = blockIdx.x * BN;
    gemm_tf32<false>(acc, g_zf, 256, 256, g_w_apfh, 192, m0, n0, nullptr, sm);
    FRAG_IDX
    #pragma unroll
    for (int mi = 0; mi < 4; mi++)
        #pragma unroll
        for (int ni = 0; ni < 4; ni++) {
            int r0 = m0 + mw + mi*16 + g, r1 = r0 + 8;
            int c0 = n0 + nw + ni*8 + t4*2, c1 = c0 + 1;
            #pragma unroll
            for (int q = 0; q < 4; q++) {
                int r = (q & 2) ? r1 : r0;
                int c = (q & 1) ? c1 : c0;
                float v = acc[mi][ni][q];
                if (c < 128)
                    g_a1[(size_t)r*128 + c] = gelu_exact(v + apb[c]);
                else if (c < 192)
                    g_f1[(size_t)r*64 + (c - 128)] = gelu_exact(v + fhb[c - 128]);
            }
        }
}

__global__ void k_ap2(const float* __restrict__ W2, const float* __restrict__ b2,
                      float* __restrict__ out) {
    __shared__ float Ws[128*SCVI_];
    __shared__ float bs[SCVI_];
    for (int i = threadIdx.x; i < 128*SCVI_; i += 256) Ws[i] = W2[i];
    if (threadIdx.x < SCVI_) bs[threadIdx.x] = b2[threadIdx.x];
    __syncthreads();
    int w = threadIdx.x >> 5, lane = threadIdx.x & 31;
    int row = blockIdx.x * 8 + w;
    float a[4];
    #pragma unroll
    for (int i = 0; i < 4; i++) a[i] = g_a1[(size_t)row*128 + lane + 32*i];
    const size_t ALIGN_OFF = 2ull * B_ROWS * G_NUM + B_ROWS;
    for (int c = 0; c < SCVI_; c++) {
        float s = 0.f;
        #pragma unroll
        for (int i = 0; i < 4; i++) s = fmaf(a[i], Ws[(lane + 32*i)*SCVI_ + c], s);
        #pragma unroll
        for (int off = 16; off; off >>= 1) s += __shfl_down_sync(0xffffffffu, s, off);
        if (lane == 0) out[ALIGN_OFF + (size_t)row*SCVI_ + c] = s + bs[c];
    }
}

__global__ void k_fh2(const float* __restrict__ W2, const float* __restrict__ b2,
                      float* __restrict__ out) {
    int w = threadIdx.x >> 5, lane = threadIdx.x & 31;
    int row = blockIdx.x * 8 + w;
    float v = g_f1[(size_t)row*64 + lane] * W2[lane]
            + g_f1[(size_t)row*64 + lane + 32] * W2[lane + 32];
    #pragma unroll
    for (int off = 16; off; off >>= 1) v += __shfl_down_sync(0xffffffffu, v, off);
    if (lane == 0) {
        const size_t FUNC_OFF = 2ull * B_ROWS * G_NUM;
        out[FUNC_OFF + row] = 1.f / (1.f + expf(-(v + b2[0])));
    }
}

// ---------------- launch ----------------
extern "C" void kernel_launch(void* const* d_in, const int* in_sizes, int n_in,
                              void* d_out, int out_size) {
    const float* vis   = (const float*)d_in[0];
    const float* pos   = (const float*)d_in[1];
    const float* grad  = (const float*)d_in[2];
    const float* lib   = (const float*)d_in[3];
    const float* fB    = (const float*)d_in[4];
    const float* img_W = (const float*)d_in[5];
    const float* img_b = (const float*)d_in[6];
    const float* pos_W = (const float*)d_in[7];
    const float* pos_b = (const float*)d_in[8];
    const float* rW    = (const float*)d_in[9];
    const float* rb    = (const float*)d_in[10];
    const float* eW1   = (const float*)d_in[11];
    const float* eb1   = (const float*)d_in[12];
    const float* eW2   = (const float*)d_in[13];
    const float* eb2   = (const float*)d_in[14];
    const float* gdW1  = (const float*)d_in[15];
    const float* gdb1  = (const float*)d_in[16];
    const float* gdg   = (const float*)d_in[17];
    const float* gdbe  = (const float*)d_in[18];
    const float* gdW2  = (const float*)d_in[19];
    const float* gdb2  = (const float*)d_in[20];
    const float* apW1  = (const float*)d_in[21];
    const float* apb1  = (const float*)d_in[22];
    const float* apW2  = (const float*)d_in[23];
    const float* apb2  = (const float*)d_in[24];
    const float* fhW1  = (const float*)d_in[25];
    const float* fhb1  = (const float*)d_in[26];
    const float* fhW2  = (const float*)d_in[27];
    const float* fhb2  = (const float*)d_in[28];
    float* out = (float*)d_out;

    static const int SM = SMEM_BYTES;
    cudaFuncSetAttribute(k_gemm_z, cudaFuncAttributeMaxDynamicSharedMemorySize, SM);
    cudaFuncSetAttribute(k_moe1,   cudaFuncAttributeMaxDynamicSharedMemorySize, SM);
    cudaFuncSetAttribute(k_moe2,   cudaFuncAttributeMaxDynamicSharedMemorySize, SM);
    cudaFuncSetAttribute(k_tpre,   cudaFuncAttributeMaxDynamicSharedMemorySize, SM);
    cudaFuncSetAttribute(k_gd2,    cudaFuncAttributeMaxDynamicSharedMemorySize, H_SMEM);
    cudaFuncSetAttribute(k_apfh,   cudaFuncAttributeMaxDynamicSharedMemorySize, SM);

    k_round_all<<<(RC6 + 255)/256, 256>>>(pos_W, img_W, eW1, eW2, gdW1, apW1, fhW1);
    k_tr_gd2   <<<dim3(NT_PAD/32, 256/32), 256>>>(gdW2);

    k_four   <<<B_ROWS/8, 256>>>(pos, fB);
    k_gemm_z <<<dim3(2, B_ROWS/BM), NTHREADS, SM>>>(vis, img_b, pos_b);
    k_router <<<B_ROWS/8, 256>>>(grad, rW, rb);
    k_offsets<<<1,1>>>();
    k_scatter<<<B_ROWS/256, 256>>>();
    k_moe1   <<<dim3(8, MAX_TILES), NTHREADS, SM>>>(eb1);
    k_moe2   <<<dim3(2, MAX_TILES), NTHREADS, SM>>>(eb2);
    k_tpre   <<<dim3(2, B_ROWS/BM), NTHREADS, SM>>>(gdb1);
    k_ln     <<<B_ROWS/8, 256>>>(gdg, gdbe);
    k_gd2    <<<dim3(NT_PAD/BN, B_ROWS/BM), NTHREADS, H_SMEM>>>(gdb2, lib, out);
    k_apfh   <<<dim3(2, B_ROWS/BM), NTHREADS, SM>>>(apb1, fhb1);
    k_ap2    <<<B_ROWS/8, 256>>>(apW2, apb2, out);
    k_fh2    <<<B_ROWS/8, 256>>>(fhW2, fhb2, out);
}

// round 15
// speedup vs baseline: 1.4415x; 1.0890x over previous
#include <cuda_runtime.h>
#include <cuda_fp16.h>
#include <cstdint>
#include <math.h>

// ---------------- problem dims ----------------
#define B_ROWS 16384
#define D_VIS  1024
#define D_H    256
#define E_NUM  4
#define G_NUM  5000
#define MAP_   128
#define SCVI_  30
#define N_GD2  (G_NUM*2)
#define NT_PAD 10112            // 79 tiles * 128

// ---------------- fp16 GEMM tile config ----------------
#define BM 128
#define BN 128
#define HBK 64                   // k-halfs per tile
#define STAGES 3
#define NTHREADS 256
#define H_AS 36                  // words per 64-half row (32 data + 4 pad)
#define H_HALF (128*H_AS)        // words per operand tile (9216/2)
#define H_STAGE (2*H_HALF)       // 9216 words
#define H_SMEM (3*H_STAGE*4)     // 110592 B -> 2 CTA/SM
#define MAX_TILES 132
#define ES_STRIDE 132

// ---------------- scratch ----------------
__device__ __half g_four_h[(size_t)B_ROWS*2*MAP_];
__device__ __half g_vis_h [(size_t)B_ROWS*D_VIS];
__device__ float  g_z     [(size_t)B_ROWS*D_H];    // fp32 for router + residual
__device__ __half g_z_h   [(size_t)B_ROWS*D_H];
__device__ __half g_zf_h  [(size_t)B_ROWS*D_H];
__device__ float  g_tpre  [(size_t)B_ROWS*D_H];
__device__ __half g_t_h   [(size_t)B_ROWS*D_H];
__device__ float  g_a1    [(size_t)B_ROWS*128];
__device__ float  g_f1    [(size_t)B_ROWS*64];
__device__ __half g_h     [(size_t)MAX_TILES*BM*1024];
__device__ int    g_eid [B_ROWS];
__device__ float  g_gate[B_ROWS];
__device__ int    g_perm[MAX_TILES*BM];
__device__ int    g_counts[E_NUM];
__device__ int    g_cursor[E_NUM];
__device__ int    g_padoff[E_NUM+1];
// transposed fp16 weights, [N][K] k-contiguous
__device__ __half w_pos_t [256*256];
__device__ __half w_img_t [256*1024];
__device__ __half w_e1_t  [E_NUM*1024*256];
__device__ __half w_e2_t  [E_NUM*256*1024];
__device__ __half w_gd1_t [256*256];
__device__ __half w_apfh_t[256*256];               // rows 0..127 ap1, 128..191 fh1, pad
__device__ __half g_wt    [(size_t)NT_PAD*256];    // gd2

// ---------------- helpers ----------------
__device__ __forceinline__ float gelu_exact(float x) {
    return 0.5f * x * (1.0f + erff(x * 0.70710678118654752440f));
}
__device__ __forceinline__ void mma16h(float* c, const uint32_t* a, const uint32_t* b) {
    asm volatile("mma.sync.aligned.m16n8k16.row.col.f32.f16.f16.f32 "
        "{%0,%1,%2,%3}, {%4,%5,%6,%7}, {%8,%9}, {%0,%1,%2,%3};"
        : "+f"(c[0]), "+f"(c[1]), "+f"(c[2]), "+f"(c[3])
        : "r"(a[0]), "r"(a[1]), "r"(a[2]), "r"(a[3]), "r"(b[0]), "r"(b[1]));
}
__device__ __forceinline__ void cp_async16(float* dst_smem, const void* src, int src_bytes) {
    uint32_t d = (uint32_t)__cvta_generic_to_shared(dst_smem);
    asm volatile("cp.async.cg.shared.global [%0], [%1], 16, %2;\n"
                 :: "r"(d), "l"(src), "r"(src_bytes));
}
__device__ __forceinline__ void cp16f(float* dst_smem, const void* src) {
    uint32_t d = (uint32_t)__cvta_generic_to_shared(dst_smem);
    asm volatile("cp.async.cg.shared.global [%0], [%1], 16;\n" :: "r"(d), "l"(src));
}
__device__ __forceinline__ void cp_commit() { asm volatile("cp.async.commit_group;\n"); }
template<int N> __device__ __forceinline__ void cp_wait() {
    asm volatile("cp.async.wait_group %0;\n" :: "n"(N));
}

// ---------------- prep kernels ----------------
// tiled transpose fp32[K][N] -> fp16[NP][K]; rows N..NP zero-filled
__global__ void k_trh(const float* __restrict__ src, __half* __restrict__ dst,
                      int K, int N, int NP, size_t sb, size_t db) {
    src += blockIdx.z * sb;
    dst += blockIdx.z * db;
    __shared__ float t[32][33];
    int n0 = blockIdx.x * 32, k0 = blockIdx.y * 32;
    int tx = threadIdx.x & 31, ty = threadIdx.x >> 5;
    #pragma unroll
    for (int i = ty; i < 32; i += 8) {
        int n = n0 + tx;
        t[i][tx] = (n < N) ? src[(size_t)(k0 + i) * N + n] : 0.f;
    }
    __syncthreads();
    #pragma unroll
    for (int i = ty; i < 32; i += 8) {
        int n = n0 + i;
        if (n < NP) dst[(size_t)n * K + k0 + tx] = __float2half_rn(t[tx][i]);
    }
}

// fp32 -> fp16 elementwise (4 per thread)
__global__ void k_vish(const float* __restrict__ src, int n4) {
    int i = blockIdx.x * blockDim.x + threadIdx.x;
    if (i >= n4) return;
    float4 v = ((const float4*)src)[i];
    __half2 a = __floats2half2_rn(v.x, v.y);
    __half2 b = __floats2half2_rn(v.z, v.w);
    uint2 o = make_uint2(*(uint32_t*)&a, *(uint32_t*)&b);
    ((uint2*)g_vis_h)[i] = o;
}

// ---------------- generic fp16 GEMM ----------------
// A [M][K] half k-contiguous; Wt [N][K] half. Warp tile 64x32, block 128x128.
template<bool PERM>
__device__ __forceinline__ void issue_h(
    float* stage, const __half* __restrict__ A, int K,
    const __half* __restrict__ Wt,
    int m0, int n0, int k0, const int* __restrict__ perm)
{
    float* As = stage;
    float* Bs = stage + H_HALF;
    const int tid = threadIdx.x;
    int r = tid >> 1;
    int jb = (tid & 1) * 4;
    if (PERM) {
        int rowg = perm[m0 + r];
        const __half* sA = A + (size_t)(rowg < 0 ? 0 : rowg) * K + k0;
        int sz = (rowg >= 0) ? 16 : 0;
        #pragma unroll
        for (int i = 0; i < 4; i++)
            cp_async16(As + r*H_AS + (jb+i)*4, sA + (jb+i)*8, sz);
    } else {
        const __half* sA = A + (size_t)(m0 + r) * K + k0;
        #pragma unroll
        for (int i = 0; i < 4; i++)
            cp16f(As + r*H_AS + (jb+i)*4, sA + (jb+i)*8);
    }
    const __half* sB = Wt + (size_t)(n0 + r) * K + k0;
    #pragma unroll
    for (int i = 0; i < 4; i++)
        cp16f(Bs + r*H_AS + (jb+i)*4, sB + (jb+i)*8);
}

template<bool PERM>
__device__ __forceinline__ void gemm_f16(
    float acc[4][4][4],
    const __half* __restrict__ A, int K,
    const __half* __restrict__ Wt,
    int m0, int n0, const int* __restrict__ perm, float* sm)
{
    const int KT = K / HBK;
    #pragma unroll
    for (int s = 0; s < STAGES-1; s++) {
        if (s < KT) issue_h<PERM>(sm + s*H_STAGE, A, K, Wt, m0, n0, s*HBK, perm);
        cp_commit();
    }
    cp_wait<STAGES-2>();
    __syncthreads();

    const int warp = threadIdx.x >> 5, lane = threadIdx.x & 31;
    const int mw = (warp >> 2) * 64, nw = (warp & 3) * 32;
    const int g = lane >> 2, t4 = lane & 3;

    for (int kt = 0; kt < KT; kt++) {
        const uint32_t* As = (const uint32_t*)(sm + (kt%STAGES)*H_STAGE);
        const uint32_t* Bs = As + H_HALF;
        #pragma unroll
        for (int s = 0; s < HBK/16; s++) {
            const int w0 = s*8 + t4;
            uint32_t af[4][4], bf[4][2];
            #pragma unroll
            for (int mi = 0; mi < 4; mi++) {
                int r = mw + mi*16 + g;
                af[mi][0] = As[(r  )*H_AS + w0];
                af[mi][1] = As[(r+8)*H_AS + w0];
                af[mi][2] = As[(r  )*H_AS + w0 + 4];
                af[mi][3] = As[(r+8)*H_AS + w0 + 4];
            }
            #pragma unroll
            for (int ni = 0; ni < 4; ni++) {
                int c = nw + ni*8 + g;
                bf[ni][0] = Bs[c*H_AS + w0];
                bf[ni][1] = Bs[c*H_AS + w0 + 4];
            }
            #pragma unroll
            for (int mi = 0; mi < 4; mi++)
                #pragma unroll
                for (int ni = 0; ni < 4; ni++)
                    mma16h(acc[mi][ni], af[mi], bf[ni]);
        }
        int pre = kt + STAGES - 1;
        if (pre < KT) issue_h<PERM>(sm + (pre%STAGES)*H_STAGE, A, K, Wt, m0, n0, pre*HBK, perm);
        cp_commit();
        cp_wait<STAGES-2>();
        __syncthreads();
    }
}

#define FRAG_IDX \
    const int warp = threadIdx.x >> 5, lane = threadIdx.x & 31; \
    const int mw = (warp >> 2) * 64, nw = (warp & 3) * 32; \
    const int g = lane >> 2, t4 = lane & 3;

// ---------------- stage kernels ----------------
__global__ void k_four(const float* __restrict__ pos, const float* __restrict__ fB) {
    int gtid = blockIdx.x * 256 + threadIdx.x;
    if (gtid < MAX_TILES*BM) g_perm[gtid] = -1;
    if (gtid < E_NUM) { g_counts[gtid] = 0; g_cursor[gtid] = 0; }

    int w = threadIdx.x >> 5, lane = threadIdx.x & 31;
    int row = blockIdx.x * 8 + w;
    float p0 = pos[row*3+0], p1 = pos[row*3+1], p2 = pos[row*3+2];
    #pragma unroll
    for (int i = 0; i < 4; i++) {
        int c = lane + 32*i;
        float xp = 6.283185307179586477f * (p0*fB[c] + p1*fB[MAP_+c] + p2*fB[2*MAP_+c]);
        float s, co;
        sincosf(xp, &s, &co);
        g_four_h[(size_t)row*256 + c]       = __float2half_rn(s);
        g_four_h[(size_t)row*256 + 128 + c] = __float2half_rn(co);
    }
}

__global__ void __launch_bounds__(NTHREADS, 2)
k_gemm_z(const float* __restrict__ img_b, const float* __restrict__ pos_b) {
    extern __shared__ float sm[];
    float acc[4][4][4] = {};
    int m0 = blockIdx.y * BM, n0 = blockIdx.x * BN;
    FRAG_IDX
    gemm_f16<false>(acc, g_four_h, 256, w_pos_t, m0, n0, nullptr, sm);
    #pragma unroll
    for (int mi = 0; mi < 4; mi++)
        #pragma unroll
        for (int ni = 0; ni < 4; ni++) {
            int c0 = n0 + nw + ni*8 + t4*2;
            acc[mi][ni][0] = gelu_exact(acc[mi][ni][0] + pos_b[c0]);
            acc[mi][ni][1] = gelu_exact(acc[mi][ni][1] + pos_b[c0+1]);
            acc[mi][ni][2] = gelu_exact(acc[mi][ni][2] + pos_b[c0]);
            acc[mi][ni][3] = gelu_exact(acc[mi][ni][3] + pos_b[c0+1]);
        }
    gemm_f16<false>(acc, g_vis_h, 1024, w_img_t, m0, n0, nullptr, sm);
    #pragma unroll
    for (int mi = 0; mi < 4; mi++)
        #pragma unroll
        for (int ni = 0; ni < 4; ni++) {
            int r0 = m0 + mw + mi*16 + g, r1 = r0 + 8;
            int c0 = n0 + nw + ni*8 + t4*2, c1 = c0 + 1;
            float v00 = acc[mi][ni][0] + img_b[c0];
            float v01 = acc[mi][ni][1] + img_b[c1];
            float v10 = acc[mi][ni][2] + img_b[c0];
            float v11 = acc[mi][ni][3] + img_b[c1];
            g_z[(size_t)r0*256 + c0] = v00;  g_z_h[(size_t)r0*256 + c0] = __float2half_rn(v00);
            g_z[(size_t)r0*256 + c1] = v01;  g_z_h[(size_t)r0*256 + c1] = __float2half_rn(v01);
            g_z[(size_t)r1*256 + c0] = v10;  g_z_h[(size_t)r1*256 + c0] = __float2half_rn(v10);
            g_z[(size_t)r1*256 + c1] = v11;  g_z_h[(size_t)r1*256 + c1] = __float2half_rn(v11);
        }
}

__global__ void k_router(const float* __restrict__ grad,
                         const float* __restrict__ rW, const float* __restrict__ rb) {
    int w = threadIdx.x >> 5, lane = threadIdx.x & 31;
    int row = blockIdx.x * 8 + w;
    float4 s = make_float4(0.f,0.f,0.f,0.f);
    #pragma unroll
    for (int i = 0; i < 8; i++) {
        int k = lane + 32*i;
        float zv = g_z[(size_t)row*256 + k];
        float4 wv = *(const float4*)(rW + k*4);
        s.x = fmaf(zv, wv.x, s.x); s.y = fmaf(zv, wv.y, s.y);
        s.z = fmaf(zv, wv.z, s.z); s.w = fmaf(zv, wv.w, s.w);
    }
    #pragma unroll
    for (int off = 16; off; off >>= 1) {
        s.x += __shfl_down_sync(0xffffffffu, s.x, off);
        s.y += __shfl_down_sync(0xffffffffu, s.y, off);
        s.z += __shfl_down_sync(0xffffffffu, s.z, off);
        s.w += __shfl_down_sync(0xffffffffu, s.w, off);
    }
    if (lane == 0) {
        float gv = grad[row];
        float4 wg = *(const float4*)(rW + 256*4);
        float l0 = s.x + gv*wg.x + rb[0];
        float l1 = s.y + gv*wg.y + rb[1];
        float l2 = s.z + gv*wg.z + rb[2];
        float l3 = s.w + gv*wg.w + rb[3];
        float m = l0; int am = 0;
        if (l1 > m) { m = l1; am = 1; }
        if (l2 > m) { m = l2; am = 2; }
        if (l3 > m) { m = l3; am = 3; }
        float sum = expf(l0-m) + expf(l1-m) + expf(l2-m) + expf(l3-m);
        g_eid[row]  = am;
        g_gate[row] = 1.0f / sum;
        atomicAdd(&g_counts[am], 1);
    }
}

__global__ void k_offsets() {
    int off = 0;
    for (int e = 0; e < E_NUM; e++) {
        g_padoff[e] = off;
        off += ((g_counts[e] + BM - 1) / BM) * BM;
    }
    g_padoff[E_NUM] = off;
}

__global__ void k_scatter() {
    int row = blockIdx.x * 256 + threadIdx.x;
    int e = g_eid[row];
    int slot = g_padoff[e] + atomicAdd(&g_cursor[e], 1);
    g_perm[slot] = row;
}

__device__ __forceinline__ int tile_expert(int m0) {
    int e = 0;
    while (e < E_NUM-1 && m0 >= g_padoff[e+1]) e++;
    return e;
}

__global__ void __launch_bounds__(NTHREADS, 2)
k_moe1(const float* __restrict__ eb1) {
    int m0 = blockIdx.y * BM;
    if (m0 >= g_padoff[E_NUM]) return;
    extern __shared__ float sm[];
    int e = tile_expert(m0);
    const __half* W1 = w_e1_t + (size_t)e * 1024 * 256;
    float acc[4][4][4] = {};
    int n0 = blockIdx.x * BN;
    gemm_f16<true>(acc, g_z_h, 256, W1, m0, n0, g_perm, sm);
    FRAG_IDX
    #pragma unroll
    for (int mi = 0; mi < 4; mi++)
        #pragma unroll
        for (int ni = 0; ni < 4; ni++) {
            int r0 = m0 + mw + mi*16 + g, r1 = r0 + 8;
            int c0 = n0 + nw + ni*8 + t4*2, c1 = c0 + 1;
            g_h[(size_t)r0*1024 + c0] = __float2half_rn(gelu_exact(acc[mi][ni][0] + eb1[e*1024 + c0]));
            g_h[(size_t)r0*1024 + c1] = __float2half_rn(gelu_exact(acc[mi][ni][1] + eb1[e*1024 + c1]));
            g_h[(size_t)r1*1024 + c0] = __float2half_rn(gelu_exact(acc[mi][ni][2] + eb1[e*1024 + c0]));
            g_h[(size_t)r1*1024 + c1] = __float2half_rn(gelu_exact(acc[mi][ni][3] + eb1[e*1024 + c1]));
        }
}

__global__ void __launch_bounds__(NTHREADS, 2)
k_moe2(const float* __restrict__ eb2) {
    int m0 = blockIdx.y * BM;
    if (m0 >= g_padoff[E_NUM]) return;
    extern __shared__ float sm[];
    int e = tile_expert(m0);
    const __half* W2 = w_e2_t + (size_t)e * 256 * 1024;
    float acc[4][4][4] = {};
    int n0 = blockIdx.x * BN;
    gemm_f16<false>(acc, g_h, 1024, W2, m0, n0, nullptr, sm);
    FRAG_IDX
    #pragma unroll
    for (int mi = 0; mi < 4; mi++)
        #pragma unroll
        for (int ni = 0; ni < 4; ni++) {
            int s0 = m0 + mw + mi*16 + g, s1 = s0 + 8;
            int c0 = n0 + nw + ni*8 + t4*2, c1 = c0 + 1;
            int r0 = g_perm[s0], r1 = g_perm[s1];
            if (r0 >= 0) {
                float gate = g_gate[r0];
                g_zf_h[(size_t)r0*256 + c0] = __float2half_rn(g_z[(size_t)r0*256 + c0] + gate*(acc[mi][ni][0] + eb2[e*256 + c0]));
                g_zf_h[(size_t)r0*256 + c1] = __float2half_rn(g_z[(size_t)r0*256 + c1] + gate*(acc[mi][ni][1] + eb2[e*256 + c1]));
            }
            if (r1 >= 0) {
                float gate = g_gate[r1];
                g_zf_h[(size_t)r1*256 + c0] = __float2half_rn(g_z[(size_t)r1*256 + c0] + gate*(acc[mi][ni][2] + eb2[e*256 + c0]));
                g_zf_h[(size_t)r1*256 + c1] = __float2half_rn(g_z[(size_t)r1*256 + c1] + gate*(acc[mi][ni][3] + eb2[e*256 + c1]));
            }
        }
}

__global__ void __launch_bounds__(NTHREADS, 2)
k_tpre(const float* __restrict__ b) {
    extern __shared__ float sm[];
    float acc[4][4][4] = {};
    int m0 = blockIdx.y * BM, n0 = blockIdx.x * BN;
    gemm_f16<false>(acc, g_zf_h, 256, w_gd1_t, m0, n0, nullptr, sm);
    FRAG_IDX
    #pragma unroll
    for (int mi = 0; mi < 4; mi++)
        #pragma unroll
        for (int ni = 0; ni < 4; ni++) {
            int r0 = m0 + mw + mi*16 + g, r1 = r0 + 8;
            int c0 = n0 + nw + ni*8 + t4*2, c1 = c0 + 1;
            g_tpre[(size_t)r0*256 + c0] = acc[mi][ni][0] + b[c0];
            g_tpre[(size_t)r0*256 + c1] = acc[mi][ni][1] + b[c1];
            g_tpre[(size_t)r1*256 + c0] = acc[mi][ni][2] + b[c0];
            g_tpre[(size_t)r1*256 + c1] = acc[mi][ni][3] + b[c1];
        }
}

__global__ void k_ln(const float* __restrict__ gam, const float* __restrict__ beta) {
    int w = threadIdx.x >> 5, lane = threadIdx.x & 31;
    int row = blockIdx.x * 8 + w;
    float v[8]; float s = 0.f;
    #pragma unroll
    for (int i = 0; i < 8; i++) {
        v[i] = g_tpre[(size_t)row*256 + lane + 32*i];
        s += v[i];
    }
    #pragma unroll
    for (int off = 16; off; off >>= 1) s += __shfl_xor_sync(0xffffffffu, s, off);
    float mean = s * (1.f/256.f);
    float s2 = 0.f;
    #pragma unroll
    for (int i = 0; i < 8; i++) { float d = v[i] - mean; s2 = fmaf(d, d, s2); }
    #pragma unroll
    for (int off = 16; off; off >>= 1) s2 += __shfl_xor_sync(0xffffffffu, s2, off);
    float rs = rsqrtf(s2 * (1.f/256.f) + 1e-5f);
    #pragma unroll
    for (int i = 0; i < 8; i++) {
        int k = lane + 32*i;
        g_t_h[(size_t)row*256 + k] = __float2half_rn(gelu_exact(gam[k] * (v[i] - mean) * rs + beta[k]));
    }
}

// gd2 with coalesced smem-staged epilogue
__global__ void __launch_bounds__(NTHREADS, 2)
k_gd2(const float* __restrict__ b2,
      const float* __restrict__ lib, float* __restrict__ out) {
    extern __shared__ float sm[];
    float acc[4][4][4] = {};
    int m0 = blockIdx.y * BM, n0 = blockIdx.x * BN;
    gemm_f16<false>(acc, g_t_h, 256, g_wt, m0, n0, nullptr, sm);
    FRAG_IDX
    float* es = sm;
    #pragma unroll
    for (int mi = 0; mi < 4; mi++)
        #pragma unroll
        for (int ni = 0; ni < 4; ni++) {
            int r0 = mw + mi*16 + g, r1 = r0 + 8;
            int c0 = nw + ni*8 + t4*2, c1 = c0 + 1;
            es[r0*ES_STRIDE + c0] = acc[mi][ni][0];
            es[r0*ES_STRIDE + c1] = acc[mi][ni][1];
            es[r1*ES_STRIDE + c0] = acc[mi][ni][2];
            es[r1*ES_STRIDE + c1] = acc[mi][ni][3];
        }
    __syncthreads();
    const size_t THETA_OFF = (size_t)B_ROWS * G_NUM;
    int gbase = n0 >> 1;
    for (int r = warp; r < BM; r += 8) {
        int row = m0 + r;
        float lb = lib[row];
        #pragma unroll
        for (int j = 0; j < 2; j++) {
            int gcol = j*32 + lane;
            int col0 = 2*gcol, col1 = col0 + 1;
            if (n0 + col0 < N_GD2) {
                float v = es[r*ES_STRIDE + col0] + b2[n0 + col0];
                float sp = (v > 20.f) ? v : log1pf(expf(v));
                out[(size_t)row*G_NUM + gbase + gcol] = sp * lb + 1e-6f;
            }
            if (n0 + col1 < N_GD2) {
                float v = es[r*ES_STRIDE + col1] + b2[n0 + col1];
                float sp = (v > 20.f) ? v : log1pf(expf(v));
                out[THETA_OFF + (size_t)row*G_NUM + gbase + gcol] = sp + 1e-6f;
            }
        }
    }
}

// merged align + func hidden: transposed padded weights [256][256]
__global__ void __launch_bounds__(NTHREADS, 2)
k_apfh(const float* __restrict__ apb, const float* __restrict__ fhb) {
    extern __shared__ float sm[];
    float acc[4][4][4] = {};
    int m0 = blockIdx.y * BM, n0 = blockIdx.x * BN;
    gemm_f16<false>(acc, g_zf_h, 256, w_apfh_t, m0, n0, nullptr, sm);
    FRAG_IDX
    #pragma unroll
    for (int mi = 0; mi < 4; mi++)
        #pragma unroll
        for (int ni = 0; ni < 4; ni++) {
            int r0 = m0 + mw + mi*16 + g, r1 = r0 + 8;
            int c0 = n0 + nw + ni*8 + t4*2, c1 = c0 + 1;
            #pragma unroll
            for (int q = 0; q < 4; q++) {
                int r = (q & 2) ? r1 : r0;
                int c = (q & 1) ? c1 : c0;
                float v = acc[mi][ni][q];
                if (c < 128)
                    g_a1[(size_t)r*128 + c] = gelu_exact(v + apb[c]);
                else if (c < 192)
                    g_f1[(size_t)r*64 + (c - 128)] = gelu_exact(v + fhb[c - 128]);
            }
        }
}

__global__ void k_ap2(const float* __restrict__ W2, const float* __restrict__ b2,
                      float* __restrict__ out) {
    __shared__ float Ws[128*SCVI_];
    __shared__ float bs[SCVI_];
    for (int i = threadIdx.x; i < 128*SCVI_; i += 256) Ws[i] = W2[i];
    if (threadIdx.x < SCVI_) bs[threadIdx.x] = b2[threadIdx.x];
    __syncthreads();
    int w = threadIdx.x >> 5, lane = threadIdx.x & 31;
    int row = blockIdx.x * 8 + w;
    float a[4];
    #pragma unroll
    for (int i = 0; i < 4; i++) a[i] = g_a1[(size_t)row*128 + lane + 32*i];
    const size_t ALIGN_OFF = 2ull * B_ROWS * G_NUM + B_ROWS;
    for (int c = 0; c < SCVI_; c++) {
        float s = 0.f;
        #pragma unroll
        for (int i = 0; i < 4; i++) s = fmaf(a[i], Ws[(lane + 32*i)*SCVI_ + c], s);
        #pragma unroll
        for (int off = 16; off; off >>= 1) s += __shfl_down_sync(0xffffffffu, s, off);
        if (lane == 0) out[ALIGN_OFF + (size_t)row*SCVI_ + c] = s + bs[c];
    }
}

__global__ void k_fh2(const float* __restrict__ W2, const float* __restrict__ b2,
                      float* __restrict__ out) {
    int w = threadIdx.x >> 5, lane = threadIdx.x & 31;
    int row = blockIdx.x * 8 + w;
    float v = g_f1[(size_t)row*64 + lane] * W2[lane]
            + g_f1[(size_t)row*64 + lane + 32] * W2[lane + 32];
    #pragma unroll
    for (int off = 16; off; off >>= 1) v += __shfl_down_sync(0xffffffffu, v, off);
    if (lane == 0) {
        const size_t FUNC_OFF = 2ull * B_ROWS * G_NUM;
        out[FUNC_OFF + row] = 1.f / (1.f + expf(-(v + b2[0])));
    }
}

// ---------------- launch ----------------
extern "C" void kernel_launch(void* const* d_in, const int* in_sizes, int n_in,
                              void* d_out, int out_size) {
    const float* vis   = (const float*)d_in[0];
    const float* pos   = (const float*)d_in[1];
    const float* grad  = (const float*)d_in[2];
    const float* lib   = (const float*)d_in[3];
    const float* fB    = (const float*)d_in[4];
    const float* img_W = (const float*)d_in[5];
    const float* img_b = (const float*)d_in[6];
    const float* pos_W = (const float*)d_in[7];
    const float* pos_b = (const float*)d_in[8];
    const float* rW    = (const float*)d_in[9];
    const float* rb    = (const float*)d_in[10];
    const float* eW1   = (const float*)d_in[11];
    const float* eb1   = (const float*)d_in[12];
    const float* eW2   = (const float*)d_in[13];
    const float* eb2   = (const float*)d_in[14];
    const float* gdW1  = (const float*)d_in[15];
    const float* gdb1  = (const float*)d_in[16];
    const float* gdg   = (const float*)d_in[17];
    const float* gdbe  = (const float*)d_in[18];
    const float* gdW2  = (const float*)d_in[19];
    const float* gdb2  = (const float*)d_in[20];
    const float* apW1  = (const float*)d_in[21];
    const float* apb1  = (const float*)d_in[22];
    const float* apW2  = (const float*)d_in[23];
    const float* apb2  = (const float*)d_in[24];
    const float* fhW1  = (const float*)d_in[25];
    const float* fhb1  = (const float*)d_in[26];
    const float* fhW2  = (const float*)d_in[27];
    const float* fhb2  = (const float*)d_in[28];
    float* out = (float*)d_out;

    cudaFuncSetAttribute(k_gemm_z, cudaFuncAttributeMaxDynamicSharedMemorySize, H_SMEM);
    cudaFuncSetAttribute(k_moe1,   cudaFuncAttributeMaxDynamicSharedMemorySize, H_SMEM);
    cudaFuncSetAttribute(k_moe2,   cudaFuncAttributeMaxDynamicSharedMemorySize, H_SMEM);
    cudaFuncSetAttribute(k_tpre,   cudaFuncAttributeMaxDynamicSharedMemorySize, H_SMEM);
    cudaFuncSetAttribute(k_gd2,    cudaFuncAttributeMaxDynamicSharedMemorySize, H_SMEM);
    cudaFuncSetAttribute(k_apfh,   cudaFuncAttributeMaxDynamicSharedMemorySize, H_SMEM);

    __half *pw, *iw, *e1w, *e2w, *g1w, *afw, *g2w;
    cudaGetSymbolAddress((void**)&pw,  w_pos_t);
    cudaGetSymbolAddress((void**)&iw,  w_img_t);
    cudaGetSymbolAddress((void**)&e1w, w_e1_t);
    cudaGetSymbolAddress((void**)&e2w, w_e2_t);
    cudaGetSymbolAddress((void**)&g1w, w_gd1_t);
    cudaGetSymbolAddress((void**)&afw, w_apfh_t);
    cudaGetSymbolAddress((void**)&g2w, g_wt);

    // weight transposes (fp32 [K][N] -> fp16 [NP][K])
    k_trh<<<dim3(8,  8, 1), 256>>>(pos_W, pw, 256, 256, 256, 0, 0);
    k_trh<<<dim3(8, 32, 1), 256>>>(img_W, iw, 1024, 256, 256, 0, 0);
    k_trh<<<dim3(32, 8, E_NUM), 256>>>(eW1, e1w, 256, 1024, 1024, (size_t)256*1024, (size_t)1024*256);
    k_trh<<<dim3(8, 32, E_NUM), 256>>>(eW2, e2w, 1024, 256, 256, (size_t)1024*256, (size_t)256*1024);
    k_trh<<<dim3(8,  8, 1), 256>>>(gdW1, g1w, 256, 256, 256, 0, 0);
    k_trh<<<dim3(316, 8, 1), 256>>>(gdW2, g2w, 256, N_GD2, NT_PAD, 0, 0);
    k_trh<<<dim3(4,  8, 1), 256>>>(apW1, afw, 256, 128, 128, 0, 0);
    k_trh<<<dim3(4,  8, 1), 256>>>(fhW1, afw + (size_t)128*256, 256, 64, 128, 0, 0);
    k_vish<<<(B_ROWS*D_VIS/4 + 255)/256, 256>>>(vis, B_ROWS*D_VIS/4);

    k_four   <<<B_ROWS/8, 256>>>(pos, fB);
    k_gemm_z <<<dim3(2, B_ROWS/BM), NTHREADS, H_SMEM>>>(img_b, pos_b);
    k_router <<<B_ROWS/8, 256>>>(grad, rW, rb);
    k_offsets<<<1,1>>>();
    k_scatter<<<B_ROWS/256, 256>>>();
    k_moe1   <<<dim3(8, MAX_TILES), NTHREADS, H_SMEM>>>(eb1);
    k_moe2   <<<dim3(2, MAX_TILES), NTHREADS, H_SMEM>>>(eb2);
    k_tpre   <<<dim3(2, B_ROWS/BM), NTHREADS, H_SMEM>>>(gdb1);
    k_ln     <<<B_ROWS/8, 256>>>(gdg, gdbe);
    k_gd2    <<<dim3(NT_PAD/BN, B_ROWS/BM), NTHREADS, H_SMEM>>>(gdb2, lib, out);
    k_apfh   <<<dim3(2, B_ROWS/BM), NTHREADS, H_SMEM>>>(apb1, fhb1);
    k_ap2    <<<B_ROWS/8, 256>>>(apW2, apb2, out);
    k_fh2    <<<B_ROWS/8, 256>>>(fhW2, fhb2, out);
}